// round 6
// baseline (speedup 1.0000x reference)
#include <cuda_runtime.h>
#include <cstddef>

// Mip chain: [6, 2048, 2048, 3] f32 -> repeated 2x2 avg pool down to 16.
// Output = concat(base, mip1..mip7).

#define R0 2048
#define OFF1 75497472ull
#define OFF2 94371840ull
#define OFF3 99090432ull
#define OFF4 100270080ull
#define OFF5 100564992ull
#define OFF6 100638720ull
#define OFF7 100657152ull

// smem layout (floats)
#define S_SLAB 0        // 8 sum-rows x 384 = 3072
#define S_M1   3072     // 8 x 192 = 1536
#define S_M2   4608     // 32 x 96 = 3072
#define S_M3   0        // reuse slab region after loop
#define S_M4   1024
#define S_M5   2048
#define S_M6   2560
#define SMEM_FLOATS 7680

// One block = 128x128 base tile -> its piece of every level incl. one mip7 px.
// Prefetch loads+L0 stores+vertical reduce happen in one phase; only 3 float4
// of vertical sums (12 regs) survive across barriers -> high occupancy.
__global__ __launch_bounds__(256, 6) void mip_all(const float* __restrict__ base,
                                                  float* __restrict__ out) {
    __shared__ float sm[SMEM_FLOATS];
    const int f  = blockIdx.z;
    const int tX = blockIdx.x;   // 0..15
    const int tY = blockIdx.y;   // 0..15
    const int t  = threadIdx.x;  // 0..255

    // Each thread owns 3 (row-pair, f4-col) units per slab:
    // unit = k*256 + t; a = unit/96 (row pair 0..7), c = unit%96 (f4 col).
    int aa[3], cc[3];
    #pragma unroll
    for (int k = 0; k < 3; k++) {
        const int unit = k * 256 + t;
        aa[k] = unit / 96;
        cc[k] = unit - aa[k] * 96;
    }

    // prologue: slab 0 load + L0 copy + vertical reduce (keep only sums)
    float4 sv[3];
    #pragma unroll
    for (int k = 0; k < 3; k++) {
        const size_t g0 = ((size_t)(f * R0 + tY * 128 + 2 * aa[k]) * R0 + tX * 128) * 3;
        const float4 va = reinterpret_cast<const float4*>(base + g0)[cc[k]];
        const float4 vb = reinterpret_cast<const float4*>(base + g0 + (size_t)R0 * 3)[cc[k]];
        reinterpret_cast<float4*>(out + g0)[cc[k]] = va;
        reinterpret_cast<float4*>(out + g0 + (size_t)R0 * 3)[cc[k]] = vb;
        sv[k].x = va.x + vb.x; sv[k].y = va.y + vb.y;
        sv[k].z = va.z + vb.z; sv[k].w = va.w + vb.w;
    }

    for (int s = 0; s < 8; s++) {
        // ---- publish this slab's vertical sums ----
        #pragma unroll
        for (int k = 0; k < 3; k++)
            reinterpret_cast<float4*>(sm + S_SLAB)[aa[k] * 96 + cc[k]] = sv[k];
        __syncthreads();

        // ---- prefetch slab s+1: load + L0 copy + reduce (loads overlap mip1/2) ----
        if (s < 7) {
            const int y0 = tY * 128 + (s + 1) * 16;
            #pragma unroll
            for (int k = 0; k < 3; k++) {
                const size_t g0 = ((size_t)(f * R0 + y0 + 2 * aa[k]) * R0 + tX * 128) * 3;
                const float4 va = reinterpret_cast<const float4*>(base + g0)[cc[k]];
                const float4 vb = reinterpret_cast<const float4*>(base + g0 + (size_t)R0 * 3)[cc[k]];
                reinterpret_cast<float4*>(out + g0)[cc[k]] = va;
                reinterpret_cast<float4*>(out + g0 + (size_t)R0 * 3)[cc[k]] = vb;
                sv[k].x = va.x + vb.x; sv[k].y = va.y + vb.y;
                sv[k].z = va.z + vb.z; sv[k].w = va.w + vb.w;
            }
        }

        // ---- mip1: 8 rows x 64 px; 2 adjacent px per thread ----
        {
            const int r1 = t >> 5;          // 0..7
            const int c1 = (t & 31) * 2;    // even
            const float* in = sm + S_SLAB + r1 * 384 + c1 * 6;  // vertical sums
            const float v0 = (in[0] + in[3]) * 0.25f;
            const float v1 = (in[1] + in[4]) * 0.25f;
            const float v2 = (in[2] + in[5]) * 0.25f;
            const float v3 = (in[6] + in[9]) * 0.25f;
            const float v4 = (in[7] + in[10]) * 0.25f;
            const float v5 = (in[8] + in[11]) * 0.25f;
            const int y1 = tY * 64 + s * 8 + r1;
            const int x1 = tX * 64 + c1;
            float2* o = reinterpret_cast<float2*>(out + OFF1 +
                          ((size_t)(f * 1024 + y1) * 1024 + x1) * 3);
            o[0] = make_float2(v0, v1);
            o[1] = make_float2(v2, v3);
            o[2] = make_float2(v4, v5);
            float* m1 = sm + S_M1 + r1 * 192 + c1 * 3;
            m1[0] = v0; m1[1] = v1; m1[2] = v2;
            m1[3] = v3; m1[4] = v4; m1[5] = v5;
        }
        __syncthreads();

        // ---- mip2: 4 rows x 32 px (threads 0..127) ----
        if (t < 128) {
            const int r2 = t >> 5;          // 0..3
            const int c2 = t & 31;
            const float* ra = sm + S_M1 + (2 * r2) * 192 + c2 * 6;
            const float* rb = ra + 192;
            const float vr = (ra[0] + ra[3] + rb[0] + rb[3]) * 0.25f;
            const float vg = (ra[1] + ra[4] + rb[1] + rb[4]) * 0.25f;
            const float vb2 = (ra[2] + ra[5] + rb[2] + rb[5]) * 0.25f;
            const int y2 = tY * 32 + s * 4 + r2;
            const int x2 = tX * 32 + c2;
            float* o = out + OFF2 + ((size_t)(f * 512 + y2) * 512 + x2) * 3;
            o[0] = vr; o[1] = vg; o[2] = vb2;
            float* m2 = sm + S_M2 + (s * 4 + r2) * 96 + c2 * 3;
            m2[0] = vr; m2[1] = vg; m2[2] = vb2;
        }
        // no barrier: next S_SLAB publish is fenced by the barrier after it,
        // and mip1 reads of S_SLAB completed before the mid-loop barrier above.
    }
    __syncthreads();

    // ---- mip3: 16x16, 1 px per thread ----
    {
        const int r = t >> 4, c = t & 15;
        const float* ra = sm + S_M2 + (2 * r) * 96 + c * 6;
        const float* rb = ra + 96;
        const float vr = (ra[0] + ra[3] + rb[0] + rb[3]) * 0.25f;
        const float vg = (ra[1] + ra[4] + rb[1] + rb[4]) * 0.25f;
        const float vb2 = (ra[2] + ra[5] + rb[2] + rb[5]) * 0.25f;
        float* o = out + OFF3 + ((size_t)(f * 256 + tY * 16 + r) * 256 + tX * 16 + c) * 3;
        o[0] = vr; o[1] = vg; o[2] = vb2;
        float* m3 = sm + S_M3 + r * 48 + c * 3;
        m3[0] = vr; m3[1] = vg; m3[2] = vb2;
    }
    __syncthreads();

    // ---- mip4: 8x8 ----
    if (t < 64) {
        const int r = t >> 3, c = t & 7;
        const float* ra = sm + S_M3 + (2 * r) * 48 + c * 6;
        const float* rb = ra + 48;
        const float vr = (ra[0] + ra[3] + rb[0] + rb[3]) * 0.25f;
        const float vg = (ra[1] + ra[4] + rb[1] + rb[4]) * 0.25f;
        const float vb2 = (ra[2] + ra[5] + rb[2] + rb[5]) * 0.25f;
        float* o = out + OFF4 + ((size_t)(f * 128 + tY * 8 + r) * 128 + tX * 8 + c) * 3;
        o[0] = vr; o[1] = vg; o[2] = vb2;
        float* m4 = sm + S_M4 + r * 24 + c * 3;
        m4[0] = vr; m4[1] = vg; m4[2] = vb2;
    }
    __syncthreads();

    // ---- mip5: 4x4 ----
    if (t < 16) {
        const int r = t >> 2, c = t & 3;
        const float* ra = sm + S_M4 + (2 * r) * 24 + c * 6;
        const float* rb = ra + 24;
        const float vr = (ra[0] + ra[3] + rb[0] + rb[3]) * 0.25f;
        const float vg = (ra[1] + ra[4] + rb[1] + rb[4]) * 0.25f;
        const float vb2 = (ra[2] + ra[5] + rb[2] + rb[5]) * 0.25f;
        float* o = out + OFF5 + ((size_t)(f * 64 + tY * 4 + r) * 64 + tX * 4 + c) * 3;
        o[0] = vr; o[1] = vg; o[2] = vb2;
        float* m5 = sm + S_M5 + r * 12 + c * 3;
        m5[0] = vr; m5[1] = vg; m5[2] = vb2;
    }
    __syncthreads();

    // ---- mip6: 2x2 ----
    if (t < 4) {
        const int r = t >> 1, c = t & 1;
        const float* ra = sm + S_M5 + (2 * r) * 12 + c * 6;
        const float* rb = ra + 12;
        const float vr = (ra[0] + ra[3] + rb[0] + rb[3]) * 0.25f;
        const float vg = (ra[1] + ra[4] + rb[1] + rb[4]) * 0.25f;
        const float vb2 = (ra[2] + ra[5] + rb[2] + rb[5]) * 0.25f;
        float* o = out + OFF6 + ((size_t)(f * 32 + tY * 2 + r) * 32 + tX * 2 + c) * 3;
        o[0] = vr; o[1] = vg; o[2] = vb2;
        float* m6 = sm + S_M6 + r * 6 + c * 3;
        m6[0] = vr; m6[1] = vg; m6[2] = vb2;
    }
    __syncthreads();

    // ---- mip7: 1 px per block ----
    if (t == 0) {
        const float* m6 = sm + S_M6;
        float* o = out + OFF7 + ((size_t)(f * 16 + tY) * 16 + tX) * 3;
        #pragma unroll
        for (int c = 0; c < 3; c++)
            o[c] = (m6[c] + m6[3 + c] + m6[6 + c] + m6[9 + c]) * 0.25f;
    }
}

extern "C" void kernel_launch(void* const* d_in, const int* in_sizes, int n_in,
                              void* d_out, int out_size) {
    const float* base = (const float*)d_in[0];
    float* out = (float*)d_out;
    dim3 g(16, 16, 6);
    mip_all<<<g, 256>>>(base, out);
}

// round 7
// speedup vs baseline: 1.2059x; 1.2059x over previous
#include <cuda_runtime.h>
#include <cstddef>
#include <cstdint>

// Mip chain: [6, 2048, 2048, 3] f32 -> repeated 2x2 avg pool down to 16.
// Output = concat(base, mip1..mip7).

#define R0 2048
#define OFF1 75497472ull
#define OFF2 94371840ull
#define OFF3 99090432ull
#define OFF4 100270080ull
#define OFF5 100564992ull
#define OFF6 100638720ull
#define OFF7 100657152ull

// smem layout (floats)
#define S_BUF0 0        // slab buffer A: 8 rows x 384 = 3072
#define S_BUF1 3072     // slab buffer B: 3072
#define S_M1   6144     // 4 x 192 = 768
#define S_M2   6912     // 32 x 96 = 3072
#define S_M3   0        // tail reuses buffer region
#define S_M4   1024
#define S_M5   2048
#define S_M6   2560
#define SMEM_FLOATS 9984

__device__ __forceinline__ void cpasync16(uint32_t dst_smem, const float* src) {
    asm volatile("cp.async.cg.shared.global [%0], [%1], 16;"
                 :: "r"(dst_smem), "l"(src));
}

// One block = 128x128 tile. Slabs of 8 rows stream via cp.async (no load regs),
// double buffered; each slab: L0 copy + mip1 + mip2; tail: mip3..mip7.
__global__ __launch_bounds__(256) void mip_all(const float* __restrict__ base,
                                               float* __restrict__ out) {
    __shared__ __align__(16) float sm[SMEM_FLOATS];
    const int f  = blockIdx.z;
    const int tX = blockIdx.x;   // 0..15
    const int tY = blockIdx.y;   // 0..15
    const int t  = threadIdx.x;  // 0..255

    const uint32_t smem_base = (uint32_t)__cvta_generic_to_shared(sm);

    // per-thread cp.async units: 8 rows x 96 f4 = 768 f4, 3 per thread
    int rw[3], cl[3];
    #pragma unroll
    for (int k = 0; k < 3; k++) {
        const int unit = k * 256 + t;
        rw[k] = unit / 96;
        cl[k] = unit - rw[k] * 96;
    }

    const size_t tile_base = ((size_t)(f * R0 + tY * 128) * R0 + tX * 128) * 3;

    // prologue: slab 0 -> buf0
    #pragma unroll
    for (int k = 0; k < 3; k++)
        cpasync16(smem_base + (uint32_t)((rw[k] * 96 + cl[k]) * 16),
                  base + tile_base + (size_t)rw[k] * (R0 * 3) + cl[k] * 4);
    asm volatile("cp.async.commit_group;");

    for (int s = 0; s < 16; s++) {
        // issue slab s+1 into the other buffer (in flight during processing)
        if (s < 15) {
            const size_t src_off = tile_base + (size_t)(s + 1) * 8 * (R0 * 3);
            const uint32_t dst = smem_base + (uint32_t)(((s + 1) & 1) * 3072 * 4);
            #pragma unroll
            for (int k = 0; k < 3; k++)
                cpasync16(dst + (uint32_t)((rw[k] * 96 + cl[k]) * 16),
                          base + src_off + (size_t)rw[k] * (R0 * 3) + cl[k] * 4);
            asm volatile("cp.async.commit_group;");
            asm volatile("cp.async.wait_group 1;");
        } else {
            asm volatile("cp.async.wait_group 0;");
        }
        __syncthreads();

        const float* buf = sm + (s & 1) * 3072;
        const size_t gslab = tile_base + (size_t)s * 8 * (R0 * 3);

        // ---- L0 copy: smem -> out, dense float4 ----
        #pragma unroll
        for (int k = 0; k < 3; k++) {
            const float4 v = reinterpret_cast<const float4*>(buf)[rw[k] * 96 + cl[k]];
            reinterpret_cast<float4*>(out + gslab + (size_t)rw[k] * (R0 * 3))[cl[k]] = v;
        }

        // ---- mip1: 4 rows x 64 px, 1 px per thread ----
        {
            const int r1 = t >> 6;         // 0..3
            const int c1 = t & 63;
            const float* pa = buf + (2 * r1) * 384 + c1 * 6;
            const float* pb = pa + 384;
            const float v0 = (pa[0] + pa[3] + pb[0] + pb[3]) * 0.25f;
            const float v1 = (pa[1] + pa[4] + pb[1] + pb[4]) * 0.25f;
            const float v2 = (pa[2] + pa[5] + pb[2] + pb[5]) * 0.25f;
            const int y1 = tY * 64 + s * 4 + r1;
            const int x1 = tX * 64 + c1;
            float* o = out + OFF1 + ((size_t)(f * 1024 + y1) * 1024 + x1) * 3;
            o[0] = v0; o[1] = v1; o[2] = v2;
            float* m1 = sm + S_M1 + r1 * 192 + c1 * 3;
            m1[0] = v0; m1[1] = v1; m1[2] = v2;
        }
        __syncthreads();

        // ---- mip2: 2 rows x 32 px (threads 0..63) ----
        if (t < 64) {
            const int r2 = t >> 5;         // 0..1
            const int c2 = t & 31;
            const float* pa = sm + S_M1 + (2 * r2) * 192 + c2 * 6;
            const float* pb = pa + 192;
            const float vr = (pa[0] + pa[3] + pb[0] + pb[3]) * 0.25f;
            const float vg = (pa[1] + pa[4] + pb[1] + pb[4]) * 0.25f;
            const float vb = (pa[2] + pa[5] + pb[2] + pb[5]) * 0.25f;
            const int y2 = tY * 32 + s * 2 + r2;
            const int x2 = tX * 32 + c2;
            float* o = out + OFF2 + ((size_t)(f * 512 + y2) * 512 + x2) * 3;
            o[0] = vr; o[1] = vg; o[2] = vb;
            float* m2 = sm + S_M2 + (s * 2 + r2) * 96 + c2 * 3;
            m2[0] = vr; m2[1] = vg; m2[2] = vb;
        }
        __syncthreads();   // buffer (s&1) free for cp.async issued next iter
    }

    // ---- mip3: 16x16, 1 px per thread ----
    {
        const int r = t >> 4, c = t & 15;
        const float* pa = sm + S_M2 + (2 * r) * 96 + c * 6;
        const float* pb = pa + 96;
        const float vr = (pa[0] + pa[3] + pb[0] + pb[3]) * 0.25f;
        const float vg = (pa[1] + pa[4] + pb[1] + pb[4]) * 0.25f;
        const float vb = (pa[2] + pa[5] + pb[2] + pb[5]) * 0.25f;
        float* o = out + OFF3 + ((size_t)(f * 256 + tY * 16 + r) * 256 + tX * 16 + c) * 3;
        o[0] = vr; o[1] = vg; o[2] = vb;
        float* m3 = sm + S_M3 + r * 48 + c * 3;
        m3[0] = vr; m3[1] = vg; m3[2] = vb;
    }
    __syncthreads();

    // ---- mip4: 8x8 ----
    if (t < 64) {
        const int r = t >> 3, c = t & 7;
        const float* pa = sm + S_M3 + (2 * r) * 48 + c * 6;
        const float* pb = pa + 48;
        const float vr = (pa[0] + pa[3] + pb[0] + pb[3]) * 0.25f;
        const float vg = (pa[1] + pa[4] + pb[1] + pb[4]) * 0.25f;
        const float vb = (pa[2] + pa[5] + pb[2] + pb[5]) * 0.25f;
        float* o = out + OFF4 + ((size_t)(f * 128 + tY * 8 + r) * 128 + tX * 8 + c) * 3;
        o[0] = vr; o[1] = vg; o[2] = vb;
        float* m4 = sm + S_M4 + r * 24 + c * 3;
        m4[0] = vr; m4[1] = vg; m4[2] = vb;
    }
    __syncthreads();

    // ---- mip5: 4x4 ----
    if (t < 16) {
        const int r = t >> 2, c = t & 3;
        const float* pa = sm + S_M4 + (2 * r) * 24 + c * 6;
        const float* pb = pa + 24;
        const float vr = (pa[0] + pa[3] + pb[0] + pb[3]) * 0.25f;
        const float vg = (pa[1] + pa[4] + pb[1] + pb[4]) * 0.25f;
        const float vb = (pa[2] + pa[5] + pb[2] + pb[5]) * 0.25f;
        float* o = out + OFF5 + ((size_t)(f * 64 + tY * 4 + r) * 64 + tX * 4 + c) * 3;
        o[0] = vr; o[1] = vg; o[2] = vb;
        float* m5 = sm + S_M5 + r * 12 + c * 3;
        m5[0] = vr; m5[1] = vg; m5[2] = vb;
    }
    __syncthreads();

    // ---- mip6: 2x2 ----
    if (t < 4) {
        const int r = t >> 1, c = t & 1;
        const float* pa = sm + S_M5 + (2 * r) * 12 + c * 6;
        const float* pb = pa + 12;
        const float vr = (pa[0] + pa[3] + pb[0] + pb[3]) * 0.25f;
        const float vg = (pa[1] + pa[4] + pb[1] + pb[4]) * 0.25f;
        const float vb = (pa[2] + pa[5] + pb[2] + pb[5]) * 0.25f;
        float* o = out + OFF6 + ((size_t)(f * 32 + tY * 2 + r) * 32 + tX * 2 + c) * 3;
        o[0] = vr; o[1] = vg; o[2] = vb;
        float* m6 = sm + S_M6 + r * 6 + c * 3;
        m6[0] = vr; m6[1] = vg; m6[2] = vb;
    }
    __syncthreads();

    // ---- mip7: 1 px per block ----
    if (t == 0) {
        const float* m6 = sm + S_M6;
        float* o = out + OFF7 + ((size_t)(f * 16 + tY) * 16 + tX) * 3;
        #pragma unroll
        for (int c = 0; c < 3; c++)
            o[c] = (m6[c] + m6[3 + c] + m6[6 + c] + m6[9 + c]) * 0.25f;
    }
}

extern "C" void kernel_launch(void* const* d_in, const int* in_sizes, int n_in,
                              void* d_out, int out_size) {
    const float* base = (const float*)d_in[0];
    float* out = (float*)d_out;
    dim3 g(16, 16, 6);
    mip_all<<<g, 256>>>(base, out);
}